// round 6
// baseline (speedup 1.0000x reference)
#include <cuda_runtime.h>
#include <cuda_fp16.h>
#include <cstdint>

// ============================================================================
// KroneckerLinear: y[t] = U^T * X_t * V  (per-token 128x128x128 GEMM pair)
// R6: dual warp-group pipeline. 512 threads = 2 groups x 8 warps; each group
// runs its own token stream with NAMED barriers only -> tensor phases of one
// group overlap LSU phases of the other (removes CTA-wide phase serialization,
// the R5 bottleneck). X staged LDG->fp16 STS (no cp.async buffer needed).
// ============================================================================

static constexpr int TOK = 16384;

// smem layout (bytes): [VT 32K | UT 32K | grp0: X16 32K, T 32K | grp1: ...]
static constexpr int OFF_VT = 0;
static constexpr int OFF_UT = 32768;
static constexpr int OFF_GRP = 65536;     // + group*65536
static constexpr int SMEM_BYTES = 196608; // 192KB -> 1 CTA/SM

__device__ __half g_Ut[16384];
__device__ __half g_Vt[16384];

// swizzled half-index of (row r, col k) in a [128x128] fp16 tile (256B rows)
__host__ __device__ __forceinline__ int himg(int r, int k) {
    return r * 128 + (k ^ ((r & 7) << 3));
}

__device__ __forceinline__ uint32_t smem_u32(const void* p) {
    uint32_t a;
    asm("{ .reg .u64 t; cvta.to.shared.u64 t, %1; cvt.u32.u64 %0, t; }"
        : "=r"(a) : "l"(p));
    return a;
}

#define LDMX4(r, addr)                                                        \
    asm volatile("ldmatrix.sync.aligned.m8n8.x4.shared.b16 {%0,%1,%2,%3}, [%4];" \
        : "=r"((r)[0]), "=r"((r)[1]), "=r"((r)[2]), "=r"((r)[3]) : "r"(addr))

#define LDMX4T(r, addr)                                                       \
    asm volatile("ldmatrix.sync.aligned.m8n8.x4.trans.shared.b16 {%0,%1,%2,%3}, [%4];" \
        : "=r"((r)[0]), "=r"((r)[1]), "=r"((r)[2]), "=r"((r)[3]) : "r"(addr))

#define MMA16816(c, a, b0, b1)                                                \
    asm volatile(                                                             \
        "mma.sync.aligned.m16n8k16.row.col.f32.f16.f16.f32 "                  \
        "{%0,%1,%2,%3},{%4,%5,%6,%7},{%8,%9},{%0,%1,%2,%3};"                  \
        : "+f"((c)[0]), "+f"((c)[1]), "+f"((c)[2]), "+f"((c)[3])              \
        : "r"((a)[0]), "r"((a)[1]), "r"((a)[2]), "r"((a)[3]), "r"(b0), "r"(b1))

#define GROUP_BAR(gid)                                                        \
    asm volatile("bar.sync %0, 256;" :: "r"((gid) + 1) : "memory")

// ---------------------------------------------------------------------------
__global__ void kron_setup(const float* __restrict__ U, const float* __restrict__ V) {
    int e = blockIdx.x * blockDim.x + threadIdx.x;
    if (e >= 16384) return;
    int n = e >> 7;
    int m = e & 127;
    g_Ut[himg(n, m)] = __float2half_rn(U[m * 128 + n]);
    g_Vt[himg(n, m)] = __float2half_rn(V[m * 128 + n]);
}

// ---------------------------------------------------------------------------
// Warp tile 32x64 (group of 8 warps covers 128x128: 4 m-groups x 2 n-groups).
// gemm_nn: C[i][j] += sum_k A[i][k]*B[j][k]; both swizzled [row][k] images.
// ---------------------------------------------------------------------------
__device__ __forceinline__ void gemm_nn(uint32_t Ab, uint32_t Bb,
                                        float c[2][8][4],
                                        int m0, int n0,
                                        uint32_t lrow, uint32_t lsw, uint32_t lk) {
    #pragma unroll
    for (int k0 = 0; k0 < 128; k0 += 16) {
        uint32_t koff = ((uint32_t)(2 * k0) + lk) ^ lsw;
        uint32_t a[2][4], b[4][4];
        #pragma unroll
        for (int mt = 0; mt < 2; mt++)
            LDMX4(a[mt], Ab + (uint32_t)(m0 + mt * 16 + lrow) * 256u + koff);
        #pragma unroll
        for (int nb = 0; nb < 4; nb++)
            LDMX4(b[nb], Bb + (uint32_t)(n0 + nb * 16 + lrow) * 256u + koff);
        #pragma unroll
        for (int mt = 0; mt < 2; mt++)
            #pragma unroll
            for (int nb = 0; nb < 4; nb++) {
                MMA16816(c[mt][2 * nb],     a[mt], b[nb][0], b[nb][2]);
                MMA16816(c[mt][2 * nb + 1], a[mt], b[nb][1], b[nb][3]);
            }
    }
}

// gemm_nt: B stored [k][j] swizzled, transposed on load. C[i][j]+=A[i][k]*B[k][j].
__device__ __forceinline__ void gemm_nt(uint32_t Ab, uint32_t Bb,
                                        float c[2][8][4],
                                        int m0, int n0,
                                        uint32_t lrow, uint32_t lsw, uint32_t lk) {
    const uint32_t ncol_lane = (uint32_t)n0 + (lk >> 1);
    #pragma unroll
    for (int k0 = 0; k0 < 128; k0 += 16) {
        uint32_t koff = ((uint32_t)(2 * k0) + lk) ^ lsw;
        uint32_t a[2][4], b[4][4];
        #pragma unroll
        for (int mt = 0; mt < 2; mt++)
            LDMX4(a[mt], Ab + (uint32_t)(m0 + mt * 16 + lrow) * 256u + koff);
        #pragma unroll
        for (int nb = 0; nb < 4; nb++) {
            uint32_t ncol = ncol_lane + (uint32_t)(nb * 16);
            LDMX4T(b[nb], Bb + (uint32_t)(k0 + lrow) * 256u + ((ncol * 2u) ^ lsw));
        }
        #pragma unroll
        for (int mt = 0; mt < 2; mt++)
            #pragma unroll
            for (int nb = 0; nb < 4; nb++) {
                MMA16816(c[mt][2 * nb],     a[mt], b[nb][0], b[nb][1]);
                MMA16816(c[mt][2 * nb + 1], a[mt], b[nb][2], b[nb][3]);
            }
    }
}

// ---------------------------------------------------------------------------
__global__ void __launch_bounds__(512, 1)
kron_main(const float* __restrict__ x, float* __restrict__ out, int ntok) {
    extern __shared__ char smem[];
    const uint32_t sb = smem_u32(smem);
    const int tid  = threadIdx.x;
    const int grp  = tid >> 8;          // 0 or 1
    const int tg_  = tid & 255;         // thread-in-group
    const int wid  = tg_ >> 5;          // warp-in-group 0..7
    const int lid  = tid & 31;
    const int g    = lid >> 2;
    const int tg4  = lid & 3;
    const int m0   = (wid & 3) * 32;    // 4 m-groups
    const int n0   = (wid >> 2) * 64;   // 2 n-groups
    const uint32_t lrow = (uint32_t)(lid & 15);
    const uint32_t lsw  = (uint32_t)((lid & 7) << 4);
    const uint32_t lk   = (uint32_t)(lid & 16);

    const uint32_t X16b = sb + OFF_GRP + (uint32_t)grp * 65536u;
    const uint32_t Tb   = X16b + 32768u;

    // Stage U^T / V^T fp16 images once (whole CTA).
    {
        const uint4* us = reinterpret_cast<const uint4*>(g_Ut);
        const uint4* vs = reinterpret_cast<const uint4*>(g_Vt);
        uint4* ud = reinterpret_cast<uint4*>(smem + OFF_UT);
        uint4* vd = reinterpret_cast<uint4*>(smem + OFF_VT);
        #pragma unroll
        for (int i = tid; i < 2048; i += 512) { ud[i] = us[i]; vd[i] = vs[i]; }
    }
    __syncthreads();   // only CTA-wide sync; groups decouple after this

    __half* xh = reinterpret_cast<__half*>(smem + (X16b - sb));
    __half* th = reinterpret_cast<__half*>(smem + (Tb - sb));

    for (int t = blockIdx.x * 2 + grp; t < ntok; t += 2 * (int)gridDim.x) {
        // ---- stage X: LDG fp32 (streaming) -> swizzled fp16 [m1][m2] ----
        {
            const float4* xs = reinterpret_cast<const float4*>(x + (size_t)t * TOK);
            #pragma unroll
            for (int it = 0; it < 16; it++) {
                int i = tg_ + it * 256;
                float4 f = __ldcs(&xs[i]);
                int m = i >> 5, k4 = (i & 31) * 4;
                __half2 lo = __floats2half2_rn(f.x, f.y);
                __half2 hi = __floats2half2_rn(f.z, f.w);
                uint2 p;
                p.x = reinterpret_cast<uint32_t&>(lo);
                p.y = reinterpret_cast<uint32_t&>(hi);
                *reinterpret_cast<uint2*>(xh + m * 128 + (k4 ^ ((m & 7) << 3))) = p;
            }
        }
        GROUP_BAR(grp);

        // ---- GEMM1: T[m1][n2] = sum_m2 X[m1][m2] * V[m2][n2] ----
        float c[2][8][4];
        #pragma unroll
        for (int i = 0; i < 2; i++)
            #pragma unroll
            for (int j = 0; j < 8; j++)
                #pragma unroll
                for (int q = 0; q < 4; q++) c[i][j][q] = 0.f;

        gemm_nn(X16b, sb + OFF_VT, c, m0, n0, lrow, lsw, lk);

        // ---- store T in natural [m1][n2] layout (conflict-free STS.32) ----
        #pragma unroll
        for (int mt = 0; mt < 2; mt++) {
            #pragma unroll
            for (int nt = 0; nt < 8; nt++) {
                int m1 = m0 + mt * 16 + g;
                int n2 = n0 + nt * 8 + 2 * tg4;
                __half2 lo = __floats2half2_rn(c[mt][nt][0], c[mt][nt][1]);
                __half2 hi = __floats2half2_rn(c[mt][nt][2], c[mt][nt][3]);
                *reinterpret_cast<__half2*>(
                    th + m1 * 128 + (n2 ^ ((m1 & 7) << 3))) = lo;
                *reinterpret_cast<__half2*>(
                    th + (m1 + 8) * 128 + (n2 ^ (((m1 + 8) & 7) << 3))) = hi;
            }
        }
        GROUP_BAR(grp);

        // ---- GEMM2: Y[n1][n2] = sum_m1 Ut[n1][m1] * T[m1][n2] (trans-B) ----
        #pragma unroll
        for (int i = 0; i < 2; i++)
            #pragma unroll
            for (int j = 0; j < 8; j++)
                #pragma unroll
                for (int q = 0; q < 4; q++) c[i][j][q] = 0.f;

        gemm_nt(sb + OFF_UT, Tb, c, m0, n0, lrow, lsw, lk);

        // ---- epilogue: Y -> gmem straight from accumulators (streaming) ----
        {
            float* o = out + (size_t)t * TOK;
            #pragma unroll
            for (int mt = 0; mt < 2; mt++) {
                int n1 = m0 + mt * 16 + g;
                #pragma unroll
                for (int nt = 0; nt < 8; nt++) {
                    int n2 = n0 + nt * 8 + 2 * tg4;
                    __stcs(reinterpret_cast<float2*>(o + n1 * 128 + n2),
                           make_float2(c[mt][nt][0], c[mt][nt][1]));
                    __stcs(reinterpret_cast<float2*>(o + (n1 + 8) * 128 + n2),
                           make_float2(c[mt][nt][2], c[mt][nt][3]));
                }
            }
        }
        GROUP_BAR(grp);   // X16/T reuse protection for next iteration
    }
}

// ---------------------------------------------------------------------------
extern "C" void kernel_launch(void* const* d_in, const int* in_sizes, int n_in,
                              void* d_out, int out_size) {
    (void)n_in; (void)out_size;
    const float* x = (const float*)d_in[0];
    const float* U = (const float*)d_in[1];
    const float* V = (const float*)d_in[2];
    float* out = (float*)d_out;
    const int ntok = in_sizes[0] / TOK;

    static int sm_count = 0;
    if (sm_count == 0) {
        cudaDeviceGetAttribute(&sm_count, cudaDevAttrMultiProcessorCount, 0);
        if (sm_count <= 0) sm_count = 148;
        cudaFuncSetAttribute(kron_main, cudaFuncAttributeMaxDynamicSharedMemorySize,
                             SMEM_BYTES);
    }
    int grid = sm_count;
    if (grid > (ntok + 1) / 2) grid = (ntok + 1) / 2;

    kron_setup<<<64, 256>>>(U, V);
    kron_main<<<grid, 512, SMEM_BYTES>>>(x, out, ntok);
}

// round 7
// speedup vs baseline: 1.0530x; 1.0530x over previous
#include <cuda_runtime.h>
#include <cuda_fp16.h>
#include <cstdint>

// ============================================================================
// KroneckerLinear: y[t] = U^T * X_t * V  (per-token 128x128x128 GEMM pair)
// R7: back to single 8-warp group + cp.async (R5 base, best), but the pure-LSU
// phases are fused INTO GEMM1's k-loop at instruction level:
//   - convert X(t+1) fp32->fp16 + cp.async issue for X(t+2): 2 chunks / k-step
//   - deferred epilogue of token t-1 (STG from kept registers): 2 pairs / k-step
// Barriers: 3 -> 2 per token. Tensor-idle LSU windows shrink to the T-store.
// ============================================================================

static constexpr int TOK = 16384;

// smem layout (bytes)
static constexpr int OFF_VT  = 0;         // V^T image [n2][m2], 32KB
static constexpr int OFF_UT  = 32768;     // U^T image [n1][m1], 32KB
static constexpr int OFF_X32 = 65536;     // raw fp32 token (cp.async), 64KB
static constexpr int OFF_X16 = 131072;    // X fp16 swizzled, 2 buffers x 32KB
static constexpr int OFF_T   = 196608;    // T image [m1][n2], 32KB
static constexpr int SMEM_BYTES = 229376; // 224KB <= 227KB cap

__device__ __half g_Ut[16384];
__device__ __half g_Vt[16384];

__host__ __device__ __forceinline__ int himg(int r, int k) {
    return r * 128 + (k ^ ((r & 7) << 3));
}

__device__ __forceinline__ uint32_t smem_u32(const void* p) {
    uint32_t a;
    asm("{ .reg .u64 t; cvta.to.shared.u64 t, %1; cvt.u32.u64 %0, t; }"
        : "=r"(a) : "l"(p));
    return a;
}

#define LDMX4(r, addr)                                                        \
    asm volatile("ldmatrix.sync.aligned.m8n8.x4.shared.b16 {%0,%1,%2,%3}, [%4];" \
        : "=r"((r)[0]), "=r"((r)[1]), "=r"((r)[2]), "=r"((r)[3]) : "r"(addr))

#define LDMX4T(r, addr)                                                       \
    asm volatile("ldmatrix.sync.aligned.m8n8.x4.trans.shared.b16 {%0,%1,%2,%3}, [%4];" \
        : "=r"((r)[0]), "=r"((r)[1]), "=r"((r)[2]), "=r"((r)[3]) : "r"(addr))

#define MMA16816(c, a, b0, b1)                                                \
    asm volatile(                                                             \
        "mma.sync.aligned.m16n8k16.row.col.f32.f16.f16.f32 "                  \
        "{%0,%1,%2,%3},{%4,%5,%6,%7},{%8,%9},{%0,%1,%2,%3};"                  \
        : "+f"((c)[0]), "+f"((c)[1]), "+f"((c)[2]), "+f"((c)[3])              \
        : "r"((a)[0]), "r"((a)[1]), "r"((a)[2]), "r"((a)[3]), "r"(b0), "r"(b1))

#define CP_ASYNC16(saddr, gptr)                                               \
    asm volatile("cp.async.cg.shared.global [%0], [%1], 16;"                  \
        :: "r"(saddr), "l"(gptr))

// ---------------------------------------------------------------------------
__global__ void kron_setup(const float* __restrict__ U, const float* __restrict__ V) {
    int e = blockIdx.x * blockDim.x + threadIdx.x;
    if (e >= 16384) return;
    int n = e >> 7;
    int m = e & 127;
    g_Ut[himg(n, m)] = __float2half_rn(U[m * 128 + n]);
    g_Vt[himg(n, m)] = __float2half_rn(V[m * 128 + n]);
}

// gemm_nt: B stored [k][j] swizzled, transposed on load (GEMM2).
__device__ __forceinline__ void gemm_nt(uint32_t Ab, uint32_t Bb,
                                        float c[4][4][4],
                                        int m0, int n0,
                                        uint32_t lrow, uint32_t lsw, uint32_t lk) {
    const uint32_t ncol_lane = (uint32_t)n0 + (lk >> 1);
    #pragma unroll
    for (int k0 = 0; k0 < 128; k0 += 16) {
        uint32_t koff = ((uint32_t)(2 * k0) + lk) ^ lsw;
        uint32_t a[4][4], b[2][4];
        #pragma unroll
        for (int mt = 0; mt < 4; mt++)
            LDMX4(a[mt], Ab + (uint32_t)(m0 + mt * 16 + lrow) * 256u + koff);
        #pragma unroll
        for (int nb = 0; nb < 2; nb++) {
            uint32_t ncol = ncol_lane + (uint32_t)(nb * 16);
            LDMX4T(b[nb], Bb + (uint32_t)(k0 + lrow) * 256u + ((ncol * 2u) ^ lsw));
        }
        #pragma unroll
        for (int mt = 0; mt < 4; mt++) {
            MMA16816(c[mt][0], a[mt], b[0][0], b[0][1]);
            MMA16816(c[mt][1], a[mt], b[0][2], b[0][3]);
            MMA16816(c[mt][2], a[mt], b[1][0], b[1][1]);
            MMA16816(c[mt][3], a[mt], b[1][2], b[1][3]);
        }
    }
}

// ---------------------------------------------------------------------------
__global__ void __launch_bounds__(256, 1)
kron_main(const float* __restrict__ x, float* __restrict__ out, int ntok) {
    extern __shared__ char smem[];
    const uint32_t sb = smem_u32(smem);
    const int tid = threadIdx.x;
    const int wid = tid >> 5;
    const int lid = tid & 31;
    const int g   = lid >> 2;
    const int tg4 = lid & 3;
    const int m0  = (wid & 1) * 64;   // 2 m-groups
    const int n0  = (wid >> 1) * 32;  // 4 n-groups
    const uint32_t lrow = (uint32_t)(lid & 15);
    const uint32_t lsw  = (uint32_t)((lid & 7) << 4);
    const uint32_t lk   = (uint32_t)(lid & 16);
    const int gstep = (int)gridDim.x;

    const uint32_t x32b = sb + OFF_X32;
    const float4*  x32f = reinterpret_cast<const float4*>(smem + OFF_X32);
    __half* th = reinterpret_cast<__half*>(smem + OFF_T);

    // Stage U^T / V^T fp16 images once.
    {
        const uint4* us = reinterpret_cast<const uint4*>(g_Ut);
        const uint4* vs = reinterpret_cast<const uint4*>(g_Vt);
        uint4* ud = reinterpret_cast<uint4*>(smem + OFF_UT);
        uint4* vd = reinterpret_cast<uint4*>(smem + OFF_VT);
        #pragma unroll
        for (int i = tid; i < 2048; i += 256) { ud[i] = us[i]; vd[i] = vs[i]; }
    }

    int t = blockIdx.x;

    // Prefetch token t, wait, convert into X16[0], prefetch token t+gstep.
    if (t < ntok) {
        const char* src = reinterpret_cast<const char*>(x + (size_t)t * TOK);
        #pragma unroll
        for (int it = 0; it < 16; it++) {
            int i = tid + it * 256;
            CP_ASYNC16(x32b + (uint32_t)i * 16u, src + (size_t)i * 16);
        }
    }
    asm volatile("cp.async.commit_group;" ::: "memory");
    asm volatile("cp.async.wait_group 0;" ::: "memory");
    __syncthreads();
    if (t < ntok) {
        __half* xh = reinterpret_cast<__half*>(smem + OFF_X16);
        const bool pf = (t + gstep) < ntok;
        const char* src2 = reinterpret_cast<const char*>(x + (size_t)(t + gstep) * TOK);
        #pragma unroll
        for (int it = 0; it < 16; it++) {
            int i = tid + it * 256;
            float4 f = x32f[i];
            int m = i >> 5, k4 = (i & 31) * 4;
            __half2 lo = __floats2half2_rn(f.x, f.y);
            __half2 hi = __floats2half2_rn(f.z, f.w);
            uint2 p;
            p.x = reinterpret_cast<uint32_t&>(lo);
            p.y = reinterpret_cast<uint32_t&>(hi);
            *reinterpret_cast<uint2*>(xh + m * 128 + (k4 ^ ((m & 7) << 3))) = p;
            if (pf) CP_ASYNC16(x32b + (uint32_t)i * 16u, src2 + (size_t)i * 16);
        }
    }
    asm volatile("cp.async.commit_group;" ::: "memory");
    __syncthreads();

    float c2[4][4][4];          // GEMM2 acc of previous token (deferred store)
    bool  have_prev = false;
    float* oprev = nullptr;
    int b = 0;

    for (; t < ntok; t += gstep, b ^= 1) {
        // x(t+gstep) must be resident in X32 before converting it below.
        asm volatile("cp.async.wait_group 0;" ::: "memory");

        const uint32_t Xcur  = sb + OFF_X16 + (uint32_t)b * 32768u;
        __half* xh_next = reinterpret_cast<__half*>(smem + OFF_X16 + (b ^ 1) * 32768);
        const bool do_conv = (t + gstep) < ntok;
        const bool do_pf   = (t + 2 * gstep) < ntok;
        const char* src2 = reinterpret_cast<const char*>(
            x + (size_t)(t + 2 * gstep) * TOK);

        // ---- GEMM1(t) with fused convert(t+1), prefetch(t+2), epilogue(t-1) ----
        float c1[4][4][4];
        #pragma unroll
        for (int i = 0; i < 4; i++)
            #pragma unroll
            for (int j = 0; j < 4; j++)
                #pragma unroll
                for (int q = 0; q < 4; q++) c1[i][j][q] = 0.f;

        #pragma unroll
        for (int ks = 0; ks < 8; ks++) {
            uint32_t koff = ((uint32_t)(32 * ks) + lk) ^ lsw;
            uint32_t a[4][4], bf[2][4];
            #pragma unroll
            for (int mt = 0; mt < 4; mt++)
                LDMX4(a[mt], Xcur + (uint32_t)(m0 + mt * 16 + lrow) * 256u + koff);
            #pragma unroll
            for (int nb = 0; nb < 2; nb++)
                LDMX4(bf[nb], sb + OFF_VT + (uint32_t)(n0 + nb * 16 + lrow) * 256u + koff);

            // fused convert: 2 chunks of 256 float4 per k-step
            if (do_conv) {
                #pragma unroll
                for (int cc = 0; cc < 2; cc++) {
                    int i = tid + (ks * 2 + cc) * 256;
                    float4 f = x32f[i];
                    int m = i >> 5, k4 = (i & 31) * 4;
                    __half2 lo = __floats2half2_rn(f.x, f.y);
                    __half2 hi = __floats2half2_rn(f.z, f.w);
                    uint2 p;
                    p.x = reinterpret_cast<uint32_t&>(lo);
                    p.y = reinterpret_cast<uint32_t&>(hi);
                    *reinterpret_cast<uint2*>(
                        xh_next + m * 128 + (k4 ^ ((m & 7) << 3))) = p;
                    if (do_pf)
                        CP_ASYNC16(x32b + (uint32_t)i * 16u, src2 + (size_t)i * 16);
                }
            }
            // fused deferred epilogue: 2 (mt,nt) pairs per k-step
            if (have_prev) {
                #pragma unroll
                for (int cc = 0; cc < 2; cc++) {
                    int p_ = ks * 2 + cc;
                    int mt = p_ >> 2, nt = p_ & 3;
                    int n1 = m0 + mt * 16 + g;
                    int n2 = n0 + nt * 8 + 2 * tg4;
                    __stcs(reinterpret_cast<float2*>(oprev + n1 * 128 + n2),
                           make_float2(c2[mt][nt][0], c2[mt][nt][1]));
                    __stcs(reinterpret_cast<float2*>(oprev + (n1 + 8) * 128 + n2),
                           make_float2(c2[mt][nt][2], c2[mt][nt][3]));
                }
            }

            #pragma unroll
            for (int mt = 0; mt < 4; mt++) {
                MMA16816(c1[mt][0], a[mt], bf[0][0], bf[0][2]);
                MMA16816(c1[mt][1], a[mt], bf[0][1], bf[0][3]);
                MMA16816(c1[mt][2], a[mt], bf[1][0], bf[1][2]);
                MMA16816(c1[mt][3], a[mt], bf[1][1], bf[1][3]);
            }
        }
        asm volatile("cp.async.commit_group;" ::: "memory");

        // ---- store T in natural [m1][n2] layout (conflict-free STS.32) ----
        #pragma unroll
        for (int mt = 0; mt < 4; mt++) {
            #pragma unroll
            for (int nt = 0; nt < 4; nt++) {
                int m1 = m0 + mt * 16 + g;
                int n2 = n0 + nt * 8 + 2 * tg4;
                __half2 lo = __floats2half2_rn(c1[mt][nt][0], c1[mt][nt][1]);
                __half2 hi = __floats2half2_rn(c1[mt][nt][2], c1[mt][nt][3]);
                *reinterpret_cast<__half2*>(
                    th + m1 * 128 + (n2 ^ ((m1 & 7) << 3))) = lo;
                *reinterpret_cast<__half2*>(
                    th + (m1 + 8) * 128 + (n2 ^ (((m1 + 8) & 7) << 3))) = hi;
            }
        }
        __syncthreads();   // T complete; X16[b^1] complete

        // ---- GEMM2(t): Y = U^T * T (trans-B); keep acc for deferred store ----
        #pragma unroll
        for (int i = 0; i < 4; i++)
            #pragma unroll
            for (int j = 0; j < 4; j++)
                #pragma unroll
                for (int q = 0; q < 4; q++) c2[i][j][q] = 0.f;

        gemm_nt(sb + OFF_UT, sb + OFF_T, c2, m0, n0, lrow, lsw, lk);

        have_prev = true;
        oprev = out + (size_t)t * TOK;
        __syncthreads();   // protect T before next iteration's T-store
    }

    // ---- drain final token's epilogue ----
    if (have_prev) {
        #pragma unroll
        for (int mt = 0; mt < 4; mt++) {
            int n1 = m0 + mt * 16 + g;
            #pragma unroll
            for (int nt = 0; nt < 4; nt++) {
                int n2 = n0 + nt * 8 + 2 * tg4;
                __stcs(reinterpret_cast<float2*>(oprev + n1 * 128 + n2),
                       make_float2(c2[mt][nt][0], c2[mt][nt][1]));
                __stcs(reinterpret_cast<float2*>(oprev + (n1 + 8) * 128 + n2),
                       make_float2(c2[mt][nt][2], c2[mt][nt][3]));
            }
        }
    }
}

// ---------------------------------------------------------------------------
extern "C" void kernel_launch(void* const* d_in, const int* in_sizes, int n_in,
                              void* d_out, int out_size) {
    (void)n_in; (void)out_size;
    const float* x = (const float*)d_in[0];
    const float* U = (const float*)d_in[1];
    const float* V = (const float*)d_in[2];
    float* out = (float*)d_out;
    const int ntok = in_sizes[0] / TOK;

    static int sm_count = 0;
    if (sm_count == 0) {
        cudaDeviceGetAttribute(&sm_count, cudaDevAttrMultiProcessorCount, 0);
        if (sm_count <= 0) sm_count = 148;
        cudaFuncSetAttribute(kron_main, cudaFuncAttributeMaxDynamicSharedMemorySize,
                             SMEM_BYTES);
    }
    int grid = sm_count < ntok ? sm_count : ntok;

    kron_setup<<<64, 256>>>(U, V);
    kron_main<<<grid, 256, SMEM_BYTES>>>(x, out, ntok);
}

// round 8
// speedup vs baseline: 1.1755x; 1.1164x over previous
#include <cuda_runtime.h>
#include <cuda_fp16.h>
#include <cstdint>

// ============================================================================
// KroneckerLinear: y[t] = U^T * X_t * V  (per-token 128x128x128 GEMM pair)
// R8: register-resident stationary operands. V-frags (GEMM1 B) and U-frags
// (GEMM2 B) are preloaded into registers ONCE before the token loop; per
// k-step only the A-side (X / T) is ldmatrix'd. GEMM2 computes Yt = T^T x Ut
// (trans-A from natural T) so U can sit on the B side.
// ============================================================================

static constexpr int TOK = 16384;

// smem layout (bytes)
static constexpr int OFF_X32 = 0;         // raw fp32 token (cp.async), 64KB
static constexpr int OFF_X16 = 65536;     // X fp16 swizzled [m1][m2], 32KB
static constexpr int OFF_T   = 98304;     // T image [m1][n2] natural, 32KB
static constexpr int OFF_VT  = 131072;    // V^T image (preamble only), 32KB
static constexpr int OFF_UT  = 163840;    // U^T image (preamble only), 32KB
static constexpr int SMEM_BYTES = 196608; // 192KB

__device__ __half g_Ut[16384];
__device__ __half g_Vt[16384];

__host__ __device__ __forceinline__ int himg(int r, int k) {
    return r * 128 + (k ^ ((r & 7) << 3));
}

__device__ __forceinline__ uint32_t smem_u32(const void* p) {
    uint32_t a;
    asm("{ .reg .u64 t; cvta.to.shared.u64 t, %1; cvt.u32.u64 %0, t; }"
        : "=r"(a) : "l"(p));
    return a;
}

#define LDMX4(r, addr)                                                        \
    asm volatile("ldmatrix.sync.aligned.m8n8.x4.shared.b16 {%0,%1,%2,%3}, [%4];" \
        : "=r"((r)[0]), "=r"((r)[1]), "=r"((r)[2]), "=r"((r)[3]) : "r"(addr))

#define LDMX4T(r, addr)                                                       \
    asm volatile("ldmatrix.sync.aligned.m8n8.x4.trans.shared.b16 {%0,%1,%2,%3}, [%4];" \
        : "=r"((r)[0]), "=r"((r)[1]), "=r"((r)[2]), "=r"((r)[3]) : "r"(addr))

#define MMA16816(c, a, b0, b1)                                                \
    asm volatile(                                                             \
        "mma.sync.aligned.m16n8k16.row.col.f32.f16.f16.f32 "                  \
        "{%0,%1,%2,%3},{%4,%5,%6,%7},{%8,%9},{%0,%1,%2,%3};"                  \
        : "+f"((c)[0]), "+f"((c)[1]), "+f"((c)[2]), "+f"((c)[3])              \
        : "r"((a)[0]), "r"((a)[1]), "r"((a)[2]), "r"((a)[3]), "r"(b0), "r"(b1))

#define CP_ASYNC16(saddr, gptr)                                               \
    asm volatile("cp.async.cg.shared.global [%0], [%1], 16;"                  \
        :: "r"(saddr), "l"(gptr))

// ---------------------------------------------------------------------------
__global__ void kron_setup(const float* __restrict__ U, const float* __restrict__ V) {
    int e = blockIdx.x * blockDim.x + threadIdx.x;
    if (e >= 16384) return;
    int n = e >> 7;
    int m = e & 127;
    g_Ut[himg(n, m)] = __float2half_rn(U[m * 128 + n]);
    g_Vt[himg(n, m)] = __float2half_rn(V[m * 128 + n]);
}

// ---------------------------------------------------------------------------
__global__ void __launch_bounds__(256, 1)
kron_main(const float* __restrict__ x, float* __restrict__ out, int ntok) {
    extern __shared__ char smem[];
    const uint32_t sb = smem_u32(smem);
    const int tid = threadIdx.x;
    const int wid = tid >> 5;
    const int lid = tid & 31;
    const int g   = lid >> 2;
    const int tg4 = lid & 3;
    const int m0  = (wid & 1) * 64;   // GEMM1: 2 m-groups (A rows)
    const int n0  = (wid >> 1) * 32;  // GEMM1: 4 n-groups (B rows)
    // GEMM2 (C = Y^T [n2][n1]): A rows = n2 (64), B rows = n1 (32)
    const int a20 = (wid & 1) * 64;   // n2 tile base
    const int b20 = (wid >> 1) * 32;  // n1 tile base
    const uint32_t lrow = (uint32_t)(lid & 15);
    const uint32_t lsw  = (uint32_t)((lid & 7) << 4);
    const uint32_t lk   = (uint32_t)(lid & 16);
    // trans-A (GEMM2) per-lane addressing: storage row/col within T
    const uint32_t arow  = (uint32_t)((lid & 7) | ((lid & 16) >> 1));
    const uint32_t asw   = (uint32_t)((lid & 7) << 4);
    const uint32_t acolh = (uint32_t)(lid & 8);
    const int gstep = (int)gridDim.x;

    const uint32_t x32b = sb + OFF_X32;
    const float4*  x32f = reinterpret_cast<const float4*>(smem + OFF_X32);
    __half* xh = reinterpret_cast<__half*>(smem + OFF_X16);
    __half* th = reinterpret_cast<__half*>(smem + OFF_T);

    // ---- preamble: stage U^T / V^T images, preload stationary fragments ----
    {
        const uint4* us = reinterpret_cast<const uint4*>(g_Ut);
        const uint4* vs = reinterpret_cast<const uint4*>(g_Vt);
        uint4* ud = reinterpret_cast<uint4*>(smem + OFF_UT);
        uint4* vd = reinterpret_cast<uint4*>(smem + OFF_VT);
        #pragma unroll
        for (int i = tid; i < 2048; i += 256) { ud[i] = us[i]; vd[i] = vs[i]; }
    }
    // prefetch first token concurrently
    int t = blockIdx.x;
    if (t < ntok) {
        const char* src = reinterpret_cast<const char*>(x + (size_t)t * TOK);
        #pragma unroll
        for (int it = 0; it < 16; it++) {
            int i = tid + it * 256;
            CP_ASYNC16(x32b + (uint32_t)i * 16u, src + (size_t)i * 16);
        }
    }
    asm volatile("cp.async.commit_group;" ::: "memory");
    __syncthreads();

    // stationary fragments: V (GEMM1 B-side), U (GEMM2 B-side). 64+64 regs.
    uint32_t vst[8][2][4], ust[8][2][4];
    #pragma unroll
    for (int ks = 0; ks < 8; ks++) {
        uint32_t koff = ((uint32_t)(32 * ks) + lk) ^ lsw;
        #pragma unroll
        for (int nb = 0; nb < 2; nb++) {
            LDMX4(vst[ks][nb],
                  sb + OFF_VT + (uint32_t)(n0 + nb * 16 + lrow) * 256u + koff);
            LDMX4(ust[ks][nb],
                  sb + OFF_UT + (uint32_t)(b20 + nb * 16 + lrow) * 256u + koff);
        }
    }

    asm volatile("cp.async.wait_group 0;" ::: "memory");
    __syncthreads();

    for (; t < ntok; t += gstep) {
        // ---- convert X32 -> X16 (swizzled fp16 [m1][m2]) ----
        #pragma unroll
        for (int it = 0; it < 16; it++) {
            int i = tid + it * 256;
            float4 f = x32f[i];
            int m = i >> 5, k4 = (i & 31) * 4;
            __half2 lo = __floats2half2_rn(f.x, f.y);
            __half2 hi = __floats2half2_rn(f.z, f.w);
            uint2 p;
            p.x = reinterpret_cast<uint32_t&>(lo);
            p.y = reinterpret_cast<uint32_t&>(hi);
            *reinterpret_cast<uint2*>(xh + m * 128 + (k4 ^ ((m & 7) << 3))) = p;
        }
        __syncthreads();

        // ---- issue cp.async for next token (hidden behind both GEMMs) ----
        {
            int tn = t + gstep;
            if (tn < ntok) {
                const char* src = reinterpret_cast<const char*>(x + (size_t)tn * TOK);
                #pragma unroll
                for (int it = 0; it < 16; it++) {
                    int i = tid + it * 256;
                    CP_ASYNC16(x32b + (uint32_t)i * 16u, src + (size_t)i * 16);
                }
            }
            asm volatile("cp.async.commit_group;" ::: "memory");
        }

        // ---- GEMM1: T[m1][n2] = sum_m2 X[m1][m2] * V[m2][n2] ----
        float c[4][4][4];
        #pragma unroll
        for (int i = 0; i < 4; i++)
            #pragma unroll
            for (int j = 0; j < 4; j++)
                #pragma unroll
                for (int q = 0; q < 4; q++) c[i][j][q] = 0.f;

        #pragma unroll
        for (int ks = 0; ks < 8; ks++) {
            uint32_t koff = ((uint32_t)(32 * ks) + lk) ^ lsw;
            uint32_t a[4][4];
            #pragma unroll
            for (int mt = 0; mt < 4; mt++)
                LDMX4(a[mt],
                      sb + OFF_X16 + (uint32_t)(m0 + mt * 16 + lrow) * 256u + koff);
            #pragma unroll
            for (int mt = 0; mt < 4; mt++) {
                MMA16816(c[mt][0], a[mt], vst[ks][0][0], vst[ks][0][2]);
                MMA16816(c[mt][1], a[mt], vst[ks][0][1], vst[ks][0][3]);
                MMA16816(c[mt][2], a[mt], vst[ks][1][0], vst[ks][1][2]);
                MMA16816(c[mt][3], a[mt], vst[ks][1][1], vst[ks][1][3]);
            }
        }

        // ---- store T natural [m1][n2] (conflict-free STS.32) ----
        #pragma unroll
        for (int mt = 0; mt < 4; mt++) {
            #pragma unroll
            for (int nt = 0; nt < 4; nt++) {
                int m1 = m0 + mt * 16 + g;
                int n2 = n0 + nt * 8 + 2 * tg4;
                __half2 lo = __floats2half2_rn(c[mt][nt][0], c[mt][nt][1]);
                __half2 hi = __floats2half2_rn(c[mt][nt][2], c[mt][nt][3]);
                *reinterpret_cast<__half2*>(
                    th + m1 * 128 + (n2 ^ ((m1 & 7) << 3))) = lo;
                *reinterpret_cast<__half2*>(
                    th + (m1 + 8) * 128 + (n2 ^ (((m1 + 8) & 7) << 3))) = hi;
            }
        }
        __syncthreads();

        // ---- GEMM2: Y^T[n2][n1] = sum_m1 T^T[n2][m1] * Ut[n1][m1] ----
        // A = T^T via ldmatrix.trans on natural T; B = stationary U frags.
        #pragma unroll
        for (int i = 0; i < 4; i++)
            #pragma unroll
            for (int j = 0; j < 4; j++)
                #pragma unroll
                for (int q = 0; q < 4; q++) c[i][j][q] = 0.f;

        #pragma unroll
        for (int ks = 0; ks < 8; ks++) {
            uint32_t a[4][4];
            #pragma unroll
            for (int at = 0; at < 4; at++) {
                // A-tile rows (n2): a20 + at*16 .. +15; k rows (m1): 16*ks..
                uint32_t srow = (uint32_t)(16 * ks) + arow;      // storage row m1
                uint32_t scol = (uint32_t)(a20 + at * 16) + acolh; // storage col n2
                LDMX4T(a[at], sb + OFF_T + srow * 256u + ((scol * 2u) ^ asw));
            }
            #pragma unroll
            for (int at = 0; at < 4; at++) {
                MMA16816(c[at][0], a[at], ust[ks][0][0], ust[ks][0][2]);
                MMA16816(c[at][1], a[at], ust[ks][0][1], ust[ks][0][3]);
                MMA16816(c[at][2], a[at], ust[ks][1][0], ust[ks][1][2]);
                MMA16816(c[at][3], a[at], ust[ks][1][1], ust[ks][1][3]);
            }
        }

        // ---- epilogue: C = Y^T[n2][n1] -> out[n1*128+n2] (scattered STG.32) ----
        {
            float* o = out + (size_t)t * TOK;
            #pragma unroll
            for (int at = 0; at < 4; at++) {
                int n2a = a20 + at * 16 + g;
                #pragma unroll
                for (int bt = 0; bt < 4; bt++) {
                    int n1a = b20 + bt * 8 + 2 * tg4;
                    __stcs(o + n1a * 128 + n2a,           c[at][bt][0]);
                    __stcs(o + (n1a + 1) * 128 + n2a,     c[at][bt][1]);
                    __stcs(o + n1a * 128 + n2a + 8,       c[at][bt][2]);
                    __stcs(o + (n1a + 1) * 128 + n2a + 8, c[at][bt][3]);
                }
            }
        }

        // next token's X32 must be resident before convert; also protects T/X16
        asm volatile("cp.async.wait_group 0;" ::: "memory");
        __syncthreads();
    }
}

// ---------------------------------------------------------------------------
extern "C" void kernel_launch(void* const* d_in, const int* in_sizes, int n_in,
                              void* d_out, int out_size) {
    (void)n_in; (void)out_size;
    const float* x = (const float*)d_in[0];
    const float* U = (const float*)d_in[1];
    const float* V = (const float*)d_in[2];
    float* out = (float*)d_out;
    const int ntok = in_sizes[0] / TOK;

    static int sm_count = 0;
    if (sm_count == 0) {
        cudaDeviceGetAttribute(&sm_count, cudaDevAttrMultiProcessorCount, 0);
        if (sm_count <= 0) sm_count = 148;
        cudaFuncSetAttribute(kron_main, cudaFuncAttributeMaxDynamicSharedMemorySize,
                             SMEM_BYTES);
    }
    int grid = sm_count < ntok ? sm_count : ntok;

    kron_setup<<<64, 256>>>(U, V);
    kron_main<<<grid, 256, SMEM_BYTES>>>(x, out, ntok);
}